// round 7
// baseline (speedup 1.0000x reference)
#include <cuda_runtime.h>

#define NN 100000
#define EE 1600000
#define FF 64
#define KK 6
#define NBLK_SCAN 98   /* ceil(NN/1024) */

// ---------------- scratch (static device globals; allocation-free) ----------
__device__ int   g_deg[NN];
__device__ float g_dinv[NN];
__device__ int   g_cnt[NN];
__device__ int   g_cursor[NN];
__device__ int   g_rowptr[NN + 1];
__device__ int   g_bsum[NBLK_SCAN];
__device__ int2  g_edge[EE];                 // packed (src, weight-bits)
__device__ float g_tx[5][(size_t)NN * FF];   // Tx1..Tx5

// ---------------- CSR build ------------------------------------------------
__global__ void zero_kernel() {
    int i = blockIdx.x * blockDim.x + threadIdx.x;
    if (i < NN) { g_deg[i] = 0; g_cnt[i] = 0; g_cursor[i] = 0; }
}

__global__ void hist_kernel(const int* __restrict__ ei) {
    int e = blockIdx.x * blockDim.x + threadIdx.x;
    if (e < EE) {
        atomicAdd(&g_deg[ei[e]], 1);        // out-degree by src (row)
        atomicAdd(&g_cnt[ei[EE + e]], 1);   // in-degree by dst (col)
    }
}

// scanA + dinv fused: 98 blocks x 1024 threads covers NN exactly
__global__ void scanA_kernel() {
    __shared__ int sh[1024];
    int t   = threadIdx.x;
    int idx = blockIdx.x * 1024 + t;

    // dinv rider (independent of the scan below; same thread range)
    if (idx < NN) {
        int d = g_deg[idx];
        g_dinv[idx] = (d > 0) ? rsqrtf((float)d) : 0.0f;
    }

    int v = (idx < NN) ? g_cnt[idx] : 0;
    sh[t] = v;
    __syncthreads();
    for (int off = 1; off < 1024; off <<= 1) {
        int tv = (t >= off) ? sh[t - off] : 0;
        __syncthreads();
        sh[t] += tv;
        __syncthreads();
    }
    if (idx < NN) g_rowptr[idx] = sh[t] - v;   // exclusive within block
    if (t == 1023) g_bsum[blockIdx.x] = sh[1023];
}

// scanB + scanC fused: each block locally prefix-sums the 98 block sums
__global__ void scanC_kernel() {
    __shared__ int s_boff[NBLK_SCAN + 1];
    if (threadIdx.x == 0) {
        int acc = 0;
#pragma unroll 1
        for (int i = 0; i < NBLK_SCAN; i++) { s_boff[i] = acc; acc += g_bsum[i]; }
        s_boff[NBLK_SCAN] = acc;
        if (blockIdx.x == 0) g_rowptr[NN] = acc;   // == EE
    }
    __syncthreads();
    int idx = blockIdx.x * blockDim.x + threadIdx.x;
    if (idx < NN) g_rowptr[idx] += s_boff[idx >> 10];
}

__global__ void scatter_kernel(const int* __restrict__ ei) {
    int e = blockIdx.x * blockDim.x + threadIdx.x;
    if (e < EE) {
        int r = ei[e];
        int c = ei[EE + e];
        int pos = g_rowptr[c] + atomicAdd(&g_cursor[c], 1);
        g_edge[pos] = make_int2(r, __float_as_int(-(g_dinv[r] * g_dinv[c])));
    }
}

// ---------------- propagation: out = alpha * (L_hat @ h) - sub -------------
// One warp per destination node; each lane owns 2 of the 64 features (float2).
// 2x manual unroll: two independent edge loads + two independent gathers in flight.
__global__ void prop_kernel(const float* __restrict__ x,
                            int h_idx, int sub_idx, float alpha, int out_idx) {
    int gw   = (blockIdx.x * blockDim.x + threadIdx.x) >> 5;
    int lane = threadIdx.x & 31;
    if (gw >= NN) return;

    const float* h = (h_idx < 0) ? x : g_tx[h_idx];
    int s = g_rowptr[gw];
    int e = g_rowptr[gw + 1];

    float ax = 0.0f, ay = 0.0f;
    int i = s;
    for (; i + 2 <= e; i += 2) {
        int2 e0 = g_edge[i];                          // lane-uniform 8B (L1 hit)
        int2 e1 = g_edge[i + 1];
        float2 h0 = ((const float2*)(h + (size_t)e0.x * FF))[lane];  // 256B/warp gather
        float2 h1 = ((const float2*)(h + (size_t)e1.x * FF))[lane];
        float w0 = __int_as_float(e0.y);
        float w1 = __int_as_float(e1.y);
        ax = fmaf(w0, h0.x, ax); ay = fmaf(w0, h0.y, ay);
        ax = fmaf(w1, h1.x, ax); ay = fmaf(w1, h1.y, ay);
    }
    if (i < e) {
        int2 ed = g_edge[i];
        float2 hv = ((const float2*)(h + (size_t)ed.x * FF))[lane];
        float wv = __int_as_float(ed.y);
        ax = fmaf(wv, hv.x, ax); ay = fmaf(wv, hv.y, ay);
    }

    float rx = alpha * ax, ry = alpha * ay;
    if (sub_idx > -2) {
        const float* sb = (sub_idx < 0) ? x : g_tx[sub_idx];
        float2 sv = ((const float2*)(sb + (size_t)gw * FF))[lane];
        rx -= sv.x; ry -= sv.y;
    }
    float2 r; r.x = rx; r.y = ry;
    ((float2*)(g_tx[out_idx] + (size_t)gw * FF))[lane] = r;
}

// ---------------- fused GEMM: out = relu(sum_k Tx_k @ W_k + b) -------------
// Exact R1 (476us) form: one thread per node row, scalar FFMA, all 6 W in smem.
__global__ __launch_bounds__(256) void gemm_kernel(const float* __restrict__ x,
                                                   const float* __restrict__ W,
                                                   const float* __restrict__ b,
                                                   float* __restrict__ out) {
    extern __shared__ float sW[];   // KK*FF*FF floats = 96 KB
    for (int i = threadIdx.x; i < KK * FF * FF; i += blockDim.x) sW[i] = W[i];
    __syncthreads();

    int node = blockIdx.x * blockDim.x + threadIdx.x;
    if (node >= NN) return;

    float acc[FF];
#pragma unroll
    for (int j = 0; j < FF; j++) acc[j] = 0.0f;

#pragma unroll 1
    for (int k = 0; k < KK; k++) {
        const float* hb = (k == 0) ? x : g_tx[k - 1];
        const float4* hr = (const float4*)(hb + (size_t)node * FF);
        const float*  wk = sW + k * FF * FF;
#pragma unroll 1
        for (int i4 = 0; i4 < FF / 4; i4++) {
            float4 xv = __ldg(hr + i4);
#pragma unroll
            for (int ii = 0; ii < 4; ii++) {
                float xs = (ii == 0) ? xv.x : (ii == 1) ? xv.y : (ii == 2) ? xv.z : xv.w;
                const float4* wr = (const float4*)(wk + (i4 * 4 + ii) * FF);
#pragma unroll
                for (int j4 = 0; j4 < FF / 4; j4++) {
                    float4 wv = wr[j4];   // broadcast across warp (no bank conflict)
                    acc[j4 * 4 + 0] = fmaf(xs, wv.x, acc[j4 * 4 + 0]);
                    acc[j4 * 4 + 1] = fmaf(xs, wv.y, acc[j4 * 4 + 1]);
                    acc[j4 * 4 + 2] = fmaf(xs, wv.z, acc[j4 * 4 + 2]);
                    acc[j4 * 4 + 3] = fmaf(xs, wv.w, acc[j4 * 4 + 3]);
                }
            }
        }
    }

    float* orow = out + (size_t)node * FF;
#pragma unroll
    for (int j4 = 0; j4 < FF / 4; j4++) {
        float4 v;
        v.x = fmaxf(acc[j4 * 4 + 0] + __ldg(b + j4 * 4 + 0), 0.0f);
        v.y = fmaxf(acc[j4 * 4 + 1] + __ldg(b + j4 * 4 + 1), 0.0f);
        v.z = fmaxf(acc[j4 * 4 + 2] + __ldg(b + j4 * 4 + 2), 0.0f);
        v.w = fmaxf(acc[j4 * 4 + 3] + __ldg(b + j4 * 4 + 3), 0.0f);
        ((float4*)orow)[j4] = v;
    }
}

// ---------------- launch ----------------------------------------------------
extern "C" void kernel_launch(void* const* d_in, const int* in_sizes, int n_in,
                              void* d_out, int out_size) {
    const float* x  = (const float*)d_in[0];   // [N, 64]
    const int*   ei = (const int*)d_in[1];     // [2, E] row-major: src then dst
    const float* W  = (const float*)d_in[2];   // [6, 64, 64]
    const float* b  = (const float*)d_in[3];   // [64]
    float* out = (float*)d_out;                // [N, 64]

    cudaFuncSetAttribute(gemm_kernel, cudaFuncAttributeMaxDynamicSharedMemorySize,
                         KK * FF * FF * (int)sizeof(float));

    const int TB = 256;
    zero_kernel   <<<(NN + TB - 1) / TB, TB>>>();        // launch 0
    hist_kernel   <<<(EE + TB - 1) / TB, TB>>>(ei);      // launch 1
    scanA_kernel  <<<NBLK_SCAN, 1024>>>();               // launch 2 (scan + dinv)
    scanC_kernel  <<<(NN + TB - 1) / TB, TB>>>();        // launch 3 (scanB + scanC)
    scatter_kernel<<<(EE + TB - 1) / TB, TB>>>(ei);      // launch 4

    int prop_blocks = (NN * 32 + TB - 1) / TB;   // warp per node
    prop_kernel<<<prop_blocks, TB>>>(x, -1, -2, 1.0f, 0);  // launch 5: Tx1 = L x
    prop_kernel<<<prop_blocks, TB>>>(x,  0, -1, 2.0f, 1);  // Tx2 = 2 L Tx1 - x
    prop_kernel<<<prop_blocks, TB>>>(x,  1,  0, 2.0f, 2);  // Tx3
    prop_kernel<<<prop_blocks, TB>>>(x,  2,  1, 2.0f, 3);  // Tx4
    prop_kernel<<<prop_blocks, TB>>>(x,  3,  2, 2.0f, 4);  // Tx5

    gemm_kernel<<<(NN + TB - 1) / TB, TB, KK * FF * FF * (int)sizeof(float)>>>(x, W, b, out);
}

// round 8
// speedup vs baseline: 1.1987x; 1.1987x over previous
#include <cuda_runtime.h>

#define NN 100000
#define EE 1600000
#define FF 64
#define KK 6
#define NBLK_SCAN 98   /* ceil(NN/1024) */

// ---------------- scratch (static device globals; allocation-free) ----------
__device__ int   g_deg[NN];
__device__ float g_dinv[NN];
__device__ int   g_cnt[NN];
__device__ int   g_cursor[NN];
__device__ int   g_rowptr[NN + 1];
__device__ int   g_bsum[NBLK_SCAN];
__device__ int   g_boff[NBLK_SCAN];
__device__ int   g_srcs[EE];
__device__ float g_wts[EE];
__device__ float g_tx[5][(size_t)NN * FF];   // Tx1..Tx5

// ---------------- CSR build ------------------------------------------------
__global__ void zero_kernel() {
    int i = blockIdx.x * blockDim.x + threadIdx.x;
    if (i < NN) { g_deg[i] = 0; g_cnt[i] = 0; g_cursor[i] = 0; }
}

__global__ void hist_kernel(const int* __restrict__ ei) {
    int e = blockIdx.x * blockDim.x + threadIdx.x;
    if (e < EE) {
        atomicAdd(&g_deg[ei[e]], 1);        // out-degree by src (row)
        atomicAdd(&g_cnt[ei[EE + e]], 1);   // in-degree by dst (col)
    }
}

__global__ void dinv_kernel() {
    int i = blockIdx.x * blockDim.x + threadIdx.x;
    if (i < NN) {
        int d = g_deg[i];
        g_dinv[i] = (d > 0) ? rsqrtf((float)d) : 0.0f;
    }
}

__global__ void scanA_kernel() {
    __shared__ int sh[1024];
    int t   = threadIdx.x;
    int idx = blockIdx.x * 1024 + t;
    int v   = (idx < NN) ? g_cnt[idx] : 0;
    sh[t] = v;
    __syncthreads();
    for (int off = 1; off < 1024; off <<= 1) {
        int tv = (t >= off) ? sh[t - off] : 0;
        __syncthreads();
        sh[t] += tv;
        __syncthreads();
    }
    if (idx < NN) g_rowptr[idx] = sh[t] - v;   // exclusive within block
    if (t == 1023) g_bsum[blockIdx.x] = sh[1023];
}

__global__ void scanB_kernel() {
    if (threadIdx.x == 0) {
        int acc = 0;
        for (int i = 0; i < NBLK_SCAN; i++) { g_boff[i] = acc; acc += g_bsum[i]; }
        g_rowptr[NN] = acc;                    // == EE
    }
}

__global__ void scanC_kernel() {
    int idx = blockIdx.x * blockDim.x + threadIdx.x;
    if (idx < NN) g_rowptr[idx] += g_boff[idx >> 10];
}

__global__ void scatter_kernel(const int* __restrict__ ei) {
    int e = blockIdx.x * blockDim.x + threadIdx.x;
    if (e < EE) {
        int r = ei[e];
        int c = ei[EE + e];
        int pos = g_rowptr[c] + atomicAdd(&g_cursor[c], 1);
        g_srcs[pos] = r;
        g_wts[pos]  = -(g_dinv[r] * g_dinv[c]);
    }
}

// ---------------- propagation: out = alpha * (L_hat @ h) - sub -------------
// One warp per destination node; each lane owns 2 of the 64 features (float2).
// EXACT R1 form — do not touch.
__global__ void prop_kernel(const float* __restrict__ x,
                            int h_idx, int sub_idx, float alpha, int out_idx) {
    int gw   = (blockIdx.x * blockDim.x + threadIdx.x) >> 5;
    int lane = threadIdx.x & 31;
    if (gw >= NN) return;

    const float* h = (h_idx < 0) ? x : g_tx[h_idx];
    int s = g_rowptr[gw];
    int e = g_rowptr[gw + 1];

    float ax = 0.0f, ay = 0.0f;
    for (int i = s; i < e; i++) {
        int   sr = g_srcs[i];                       // lane-uniform broadcast
        float wv = g_wts[i];
        float2 hv = ((const float2*)(h + (size_t)sr * FF))[lane];  // 256B coalesced
        ax = fmaf(wv, hv.x, ax);
        ay = fmaf(wv, hv.y, ay);
    }
    float rx = alpha * ax, ry = alpha * ay;
    if (sub_idx > -2) {
        const float* sb = (sub_idx < 0) ? x : g_tx[sub_idx];
        float2 sv = ((const float2*)(sb + (size_t)gw * FF))[lane];
        rx -= sv.x; ry -= sv.y;
    }
    float2 r; r.x = rx; r.y = ry;
    ((float2*)(g_tx[out_idx] + (size_t)gw * FF))[lane] = r;
}

// ---------------- fused GEMM: out = relu(sum_k Tx_k @ W_k + b) -------------
// One thread per node row; all 6 W matrices in dynamic shared (broadcast LDS).
// ONLY change vs R1: inner product uses packed fma.rn.f32x2 (SASS FFMA2),
// halving FMA-pipe issue slots. 32 independent u64 accumulators, regs capped.
__global__ __launch_bounds__(256, 2) void gemm_kernel(const float* __restrict__ x,
                                                      const float* __restrict__ W,
                                                      const float* __restrict__ b,
                                                      float* __restrict__ out) {
    extern __shared__ float sW[];   // KK*FF*FF floats = 96 KB
    for (int i = threadIdx.x; i < KK * FF * FF; i += blockDim.x) sW[i] = W[i];
    __syncthreads();

    int node = blockIdx.x * blockDim.x + threadIdx.x;
    if (node >= NN) return;

    unsigned long long acc[FF / 2];   // 32 packed (f32,f32) accumulators
#pragma unroll
    for (int j = 0; j < FF / 2; j++) acc[j] = 0ULL;

#pragma unroll 1
    for (int k = 0; k < KK; k++) {
        const float* hb = (k == 0) ? x : g_tx[k - 1];
        const float4* hr = (const float4*)(hb + (size_t)node * FF);
        const float*  wk = sW + k * FF * FF;
#pragma unroll 1
        for (int i4 = 0; i4 < FF / 4; i4++) {
            float4 xv = __ldg(hr + i4);
#pragma unroll
            for (int ii = 0; ii < 4; ii++) {
                float xs = (ii == 0) ? xv.x : (ii == 1) ? xv.y : (ii == 2) ? xv.z : xv.w;
                unsigned long long xx;
                asm("mov.b64 %0, {%1, %1};" : "=l"(xx) : "f"(xs));
                const ulonglong2* wr = (const ulonglong2*)(wk + (i4 * 4 + ii) * FF);
#pragma unroll
                for (int j4 = 0; j4 < FF / 4; j4++) {
                    ulonglong2 wv = wr[j4];   // broadcast LDS.128 (no bank conflict)
                    asm("fma.rn.f32x2 %0, %1, %2, %0;"
                        : "+l"(acc[2 * j4])     : "l"(xx), "l"(wv.x));
                    asm("fma.rn.f32x2 %0, %1, %2, %0;"
                        : "+l"(acc[2 * j4 + 1]) : "l"(xx), "l"(wv.y));
                }
            }
        }
    }

    float* orow = out + (size_t)node * FF;
#pragma unroll
    for (int j = 0; j < FF / 2; j++) {
        float alo = __uint_as_float((unsigned int)(acc[j] & 0xffffffffULL));
        float ahi = __uint_as_float((unsigned int)(acc[j] >> 32));
        float2 v;
        v.x = fmaxf(alo + __ldg(b + 2 * j),     0.0f);
        v.y = fmaxf(ahi + __ldg(b + 2 * j + 1), 0.0f);
        ((float2*)orow)[j] = v;
    }
}

// ---------------- launch ----------------------------------------------------
extern "C" void kernel_launch(void* const* d_in, const int* in_sizes, int n_in,
                              void* d_out, int out_size) {
    const float* x  = (const float*)d_in[0];   // [N, 64]
    const int*   ei = (const int*)d_in[1];     // [2, E] row-major: src then dst
    const float* W  = (const float*)d_in[2];   // [6, 64, 64]
    const float* b  = (const float*)d_in[3];   // [64]
    float* out = (float*)d_out;                // [N, 64]

    cudaFuncSetAttribute(gemm_kernel, cudaFuncAttributeMaxDynamicSharedMemorySize,
                         KK * FF * FF * (int)sizeof(float));

    const int TB = 256;
    zero_kernel   <<<(NN + TB - 1) / TB, TB>>>();
    hist_kernel   <<<(EE + TB - 1) / TB, TB>>>(ei);
    dinv_kernel   <<<(NN + TB - 1) / TB, TB>>>();
    scanA_kernel  <<<NBLK_SCAN, 1024>>>();
    scanB_kernel  <<<1, 32>>>();
    scanC_kernel  <<<(NN + TB - 1) / TB, TB>>>();
    scatter_kernel<<<(EE + TB - 1) / TB, TB>>>(ei);

    int prop_blocks = (NN * 32 + TB - 1) / TB;   // warp per node
    prop_kernel<<<prop_blocks, TB>>>(x, -1, -2, 1.0f, 0);  // Tx1 = L x
    prop_kernel<<<prop_blocks, TB>>>(x,  0, -1, 2.0f, 1);  // Tx2 = 2 L Tx1 - x
    prop_kernel<<<prop_blocks, TB>>>(x,  1,  0, 2.0f, 2);  // Tx3
    prop_kernel<<<prop_blocks, TB>>>(x,  2,  1, 2.0f, 3);  // Tx4
    prop_kernel<<<prop_blocks, TB>>>(x,  3,  2, 2.0f, 4);  // Tx5

    gemm_kernel<<<(NN + TB - 1) / TB, TB, KK * FF * FF * (int)sizeof(float)>>>(x, W, b, out);
}

// round 11
// speedup vs baseline: 1.5472x; 1.2907x over previous
#include <cuda_runtime.h>
#include <cuda_bf16.h>
#include <mma.h>
#include <cstdint>

using namespace nvcuda;

#define NN 100000
#define EE 1600000
#define FF 64
#define KK 6
#define NBLK_SCAN 98   /* ceil(NN/1024) */

// ---------------- scratch (static device globals; allocation-free) ----------
__device__ int   g_deg[NN];
__device__ float g_dinv[NN];
__device__ int   g_cnt[NN];
__device__ int   g_cursor[NN];
__device__ int   g_rowptr[NN + 1];
__device__ int   g_bsum[NBLK_SCAN];
__device__ int   g_boff[NBLK_SCAN];
__device__ int   g_srcs[EE];
__device__ float g_wts[EE];
__device__ float g_tx[5][(size_t)NN * FF];   // Tx1..Tx5

// ---------------- CSR build (EXACT R1) --------------------------------------
__global__ void zero_kernel() {
    int i = blockIdx.x * blockDim.x + threadIdx.x;
    if (i < NN) { g_deg[i] = 0; g_cnt[i] = 0; g_cursor[i] = 0; }
}

__global__ void hist_kernel(const int* __restrict__ ei) {
    int e = blockIdx.x * blockDim.x + threadIdx.x;
    if (e < EE) {
        atomicAdd(&g_deg[ei[e]], 1);
        atomicAdd(&g_cnt[ei[EE + e]], 1);
    }
}

__global__ void dinv_kernel() {
    int i = blockIdx.x * blockDim.x + threadIdx.x;
    if (i < NN) {
        int d = g_deg[i];
        g_dinv[i] = (d > 0) ? rsqrtf((float)d) : 0.0f;
    }
}

__global__ void scanA_kernel() {
    __shared__ int sh[1024];
    int t   = threadIdx.x;
    int idx = blockIdx.x * 1024 + t;
    int v   = (idx < NN) ? g_cnt[idx] : 0;
    sh[t] = v;
    __syncthreads();
    for (int off = 1; off < 1024; off <<= 1) {
        int tv = (t >= off) ? sh[t - off] : 0;
        __syncthreads();
        sh[t] += tv;
        __syncthreads();
    }
    if (idx < NN) g_rowptr[idx] = sh[t] - v;
    if (t == 1023) g_bsum[blockIdx.x] = sh[1023];
}

__global__ void scanB_kernel() {
    if (threadIdx.x == 0) {
        int acc = 0;
        for (int i = 0; i < NBLK_SCAN; i++) { g_boff[i] = acc; acc += g_bsum[i]; }
        g_rowptr[NN] = acc;
    }
}

__global__ void scanC_kernel() {
    int idx = blockIdx.x * blockDim.x + threadIdx.x;
    if (idx < NN) g_rowptr[idx] += g_boff[idx >> 10];
}

__global__ void scatter_kernel(const int* __restrict__ ei) {
    int e = blockIdx.x * blockDim.x + threadIdx.x;
    if (e < EE) {
        int r = ei[e];
        int c = ei[EE + e];
        int pos = g_rowptr[c] + atomicAdd(&g_cursor[c], 1);
        g_srcs[pos] = r;
        g_wts[pos]  = -(g_dinv[r] * g_dinv[c]);
    }
}

// ---------------- propagation (EXACT R1) -------------------------------------
__global__ void prop_kernel(const float* __restrict__ x,
                            int h_idx, int sub_idx, float alpha, int out_idx) {
    int gw   = (blockIdx.x * blockDim.x + threadIdx.x) >> 5;
    int lane = threadIdx.x & 31;
    if (gw >= NN) return;

    const float* h = (h_idx < 0) ? x : g_tx[h_idx];
    int s = g_rowptr[gw];
    int e = g_rowptr[gw + 1];

    float ax = 0.0f, ay = 0.0f;
    for (int i = s; i < e; i++) {
        int   sr = g_srcs[i];
        float wv = g_wts[i];
        float2 hv = ((const float2*)(h + (size_t)sr * FF))[lane];
        ax = fmaf(wv, hv.x, ax);
        ay = fmaf(wv, hv.y, ay);
    }
    float rx = alpha * ax, ry = alpha * ay;
    if (sub_idx > -2) {
        const float* sb = (sub_idx < 0) ? x : g_tx[sub_idx];
        float2 sv = ((const float2*)(sb + (size_t)gw * FF))[lane];
        rx -= sv.x; ry -= sv.y;
    }
    float2 r; r.x = rx; r.y = ry;
    ((float2*)(g_tx[out_idx] + (size_t)gw * FF))[lane] = r;
}

// ================= wmma bf16 GEMM: out = relu(sum_k Tx_k @ W_k + b) =========
// CTA = 256 threads / 8 warps; tile = 32 nodes x 64 outs (NN = 3125*32 exact).
// 2-term bf16 split (hh + hl + lh) for fp32-class accuracy on the HMMA pipe.

#define APAD 72   /* bf16 row stride for A/W smem tiles (bank-conflict pad) */

__device__ __forceinline__ void wm_split(float v, __nv_bfloat16& h, __nv_bfloat16& l) {
    h = __float2bfloat16(v);
    l = __float2bfloat16(v - __bfloat162float(h));
}

__global__ __launch_bounds__(256) void wmma_gemm_kernel(const float* __restrict__ x,
                                                        const float* __restrict__ W,
                                                        const float* __restrict__ b,
                                                        float* __restrict__ out) {
    __shared__ __nv_bfloat16 sAhi[32 * APAD];
    __shared__ __nv_bfloat16 sAlo[32 * APAD];
    __shared__ __nv_bfloat16 sWhi[64 * APAD];
    __shared__ __nv_bfloat16 sWlo[64 * APAD];
    __shared__ float         sOut[32 * 64];

    int tid  = threadIdx.x;
    int warp = tid >> 5;
    int m0   = blockIdx.x * 32;

    int w_m = (warp >> 2) * 16;     // 0 or 16: node-subtile row
    int w_n = (warp & 3) * 16;      // 0,16,32,48: out-feature subtile col

    wmma::fragment<wmma::accumulator, 16, 16, 16, float> acc;
    wmma::fill_fragment(acc, 0.0f);

#pragma unroll 1
    for (int k = 0; k < KK; k++) {
        // ---- stage A tile: 32 nodes x 64 features, fp32 -> bf16 hi/lo ----
        const float* hb = (k == 0) ? x : g_tx[k - 1];
        for (int idx = tid; idx < 32 * 16; idx += 256) {
            int r = idx >> 4, c4 = idx & 15;
            float4 v = __ldg((const float4*)(hb + (size_t)(m0 + r) * FF) + c4);
            __nv_bfloat16 h0, l0, h1, l1, h2, l2, h3, l3;
            wm_split(v.x, h0, l0); wm_split(v.y, h1, l1);
            wm_split(v.z, h2, l2); wm_split(v.w, h3, l3);
            int o = r * APAD + c4 * 4;
            sAhi[o] = h0; sAhi[o+1] = h1; sAhi[o+2] = h2; sAhi[o+3] = h3;
            sAlo[o] = l0; sAlo[o+1] = l1; sAlo[o+2] = l2; sAlo[o+3] = l3;
        }
        // ---- stage W_k: 64x64 row-major (in x out) -> bf16 hi/lo ----
        for (int idx = tid; idx < 64 * 16; idx += 256) {
            int r = idx >> 4, c4 = idx & 15;
            float4 v = __ldg((const float4*)(W + k * FF * FF + r * FF) + c4);
            __nv_bfloat16 h0, l0, h1, l1, h2, l2, h3, l3;
            wm_split(v.x, h0, l0); wm_split(v.y, h1, l1);
            wm_split(v.z, h2, l2); wm_split(v.w, h3, l3);
            int o = r * APAD + c4 * 4;
            sWhi[o] = h0; sWhi[o+1] = h1; sWhi[o+2] = h2; sWhi[o+3] = h3;
            sWlo[o] = l0; sWlo[o+1] = l1; sWlo[o+2] = l2; sWlo[o+3] = l3;
        }
        __syncthreads();

        // ---- 4 k-chunks x 3 split products ----
#pragma unroll
        for (int kk = 0; kk < 4; kk++) {
            wmma::fragment<wmma::matrix_a, 16, 16, 16, __nv_bfloat16, wmma::row_major> a_hi, a_lo;
            wmma::fragment<wmma::matrix_b, 16, 16, 16, __nv_bfloat16, wmma::row_major> b_hi, b_lo;
            wmma::load_matrix_sync(a_hi, &sAhi[w_m * APAD + kk * 16], APAD);
            wmma::load_matrix_sync(a_lo, &sAlo[w_m * APAD + kk * 16], APAD);
            wmma::load_matrix_sync(b_hi, &sWhi[(kk * 16) * APAD + w_n], APAD);
            wmma::load_matrix_sync(b_lo, &sWlo[(kk * 16) * APAD + w_n], APAD);
            wmma::mma_sync(acc, a_hi, b_hi, acc);
            wmma::mma_sync(acc, a_hi, b_lo, acc);
            wmma::mma_sync(acc, a_lo, b_hi, acc);
        }
        __syncthreads();   // before restaging smem for next k
    }

    // ---- epilogue: frag -> smem, bias + relu, float4 stores ----
    wmma::store_matrix_sync(&sOut[w_m * 64 + w_n], acc, 64, wmma::mem_row_major);
    __syncthreads();

    for (int idx = tid; idx < 32 * 16; idx += 256) {
        int r = idx >> 4, c4 = idx & 15;
        float4 v = ((const float4*)(sOut + r * 64))[c4];
        v.x = fmaxf(v.x + __ldg(b + c4 * 4 + 0), 0.0f);
        v.y = fmaxf(v.y + __ldg(b + c4 * 4 + 1), 0.0f);
        v.z = fmaxf(v.z + __ldg(b + c4 * 4 + 2), 0.0f);
        v.w = fmaxf(v.w + __ldg(b + c4 * 4 + 3), 0.0f);
        ((float4*)(out + (size_t)(m0 + r) * FF))[c4] = v;
    }
}

// ---------------- launch ----------------------------------------------------
extern "C" void kernel_launch(void* const* d_in, const int* in_sizes, int n_in,
                              void* d_out, int out_size) {
    const float* x  = (const float*)d_in[0];   // [N, 64]
    const int*   ei = (const int*)d_in[1];     // [2, E]: src row then dst row
    const float* W  = (const float*)d_in[2];   // [6, 64, 64]
    const float* b  = (const float*)d_in[3];   // [64]
    float* out = (float*)d_out;                // [N, 64]

    const int TB = 256;
    zero_kernel   <<<(NN + TB - 1) / TB, TB>>>();
    hist_kernel   <<<(EE + TB - 1) / TB, TB>>>(ei);
    dinv_kernel   <<<(NN + TB - 1) / TB, TB>>>();
    scanA_kernel  <<<NBLK_SCAN, 1024>>>();
    scanB_kernel  <<<1, 32>>>();
    scanC_kernel  <<<(NN + TB - 1) / TB, TB>>>();
    scatter_kernel<<<(EE + TB - 1) / TB, TB>>>(ei);

    int prop_blocks = (NN * 32 + TB - 1) / TB;   // warp per node
    prop_kernel<<<prop_blocks, TB>>>(x, -1, -2, 1.0f, 0);  // Tx1 = L x
    prop_kernel<<<prop_blocks, TB>>>(x,  0, -1, 2.0f, 1);  // Tx2 = 2 L Tx1 - x
    prop_kernel<<<prop_blocks, TB>>>(x,  1,  0, 2.0f, 2);  // Tx3
    prop_kernel<<<prop_blocks, TB>>>(x,  2,  1, 2.0f, 3);  // Tx4
    prop_kernel<<<prop_blocks, TB>>>(x,  3,  2, 2.0f, 4);  // Tx5

    wmma_gemm_kernel<<<NN / 32, TB>>>(x, W, b, out);   // 3125 CTAs, exact
}